// round 12
// baseline (speedup 1.0000x reference)
#include <cuda_runtime.h>
#include <cuda_fp16.h>
#include <cstdint>

#define NN 100000
#define EE 1600000
#define FD 64
#define NHD 8
#define CDIV(a,b) (((a)+(b)-1)/(b))

// ---------------- scratch ----------------
static __device__ __align__(16) float  g_dinv[NN];
static __device__ __align__(16) __half g_t  [NN*FD];     // GEMM output (messages)
static __device__ __align__(16) __half g_h  [NN*FD];     // layer activations (fp16)
static __device__ __align__(16) __half g_w16[20480];     // W0(8192) Wg(4096) W2(4096) W3(4096)
static __device__ __align__(16) float  g_as [NN*NHD];
static __device__ __align__(16) float  g_ad [NN*NHD];
static __device__ int g_deg[NN];
static __device__ int g_rowbeg[NN];
static __device__ int g_cursor[NN];
static __device__ int g_csrc[EE];
static __device__ int g_total;

__device__ __forceinline__ float lrelu(float x) { return x > 0.f ? x : 0.2f * x; }
__device__ __forceinline__ uint32_t qpack(float a, float b) {
    __half2 h = __float22half2_rn(make_float2(a, b));
    return *(uint32_t*)&h;
}

// ---------------- weight conversion + counter zero ----------------
__global__ void k_w2h(const float* __restrict__ W0, const float* __restrict__ Wg,
                      const float* __restrict__ W2, const float* __restrict__ W3) {
    int i = blockIdx.x * blockDim.x + threadIdx.x;
    if (i == 0) g_total = 0;
    if (i < NN) g_deg[i] = 0;
    if (i < 8192) g_w16[i] = __float2half(W0[i]);
    if (i < 4096) {
        g_w16[8192  + i] = __float2half(Wg[i]);
        g_w16[12288 + i] = __float2half(W2[i]);
        g_w16[16384 + i] = __float2half(W3[i]);
    }
}

// ---------------- CSR build (atomic segment allocation — no prefix sum) ----------------
__global__ void k_deg(const int* __restrict__ dst) {
    int e = blockIdx.x * blockDim.x + threadIdx.x;
    if (e < EE) atomicAdd(&g_deg[dst[e]], 1);
}
__global__ void __launch_bounds__(256) k_alloc() {
    int i = blockIdx.x * blockDim.x + threadIdx.x;
    int lane = threadIdx.x & 31;
    int dg = (i < NN) ? g_deg[i] : 0;
    if (i < NN) g_dinv[i] = rsqrtf((float)(dg + 1));
    // warp inclusive scan of dg
    int incl = dg;
#pragma unroll
    for (int o = 1; o < 32; o <<= 1) {
        int y = __shfl_up_sync(~0u, incl, o);
        if (lane >= o) incl += y;
    }
    int wsum = __shfl_sync(~0u, incl, 31);
    int base = 0;
    if (lane == 31) base = atomicAdd(&g_total, wsum);
    base = __shfl_sync(~0u, base, 31);
    int beg = base + incl - dg;
    if (i < NN) { g_rowbeg[i] = beg; g_cursor[i] = beg; }
}
__global__ void k_scatter(const int* __restrict__ src, const int* __restrict__ dst) {
    int e = blockIdx.x * blockDim.x + threadIdx.x;
    if (e >= EE) return;
    int pos = atomicAdd(&g_cursor[dst[e]], 1);
    g_csrc[pos] = src[e];
}

// ---------------- tensor-core GEMM: [NN,K]x[K,64] -> fp16 [NN,64] ----------------
__device__ __forceinline__ void ldsm4(uint32_t a, uint32_t& r0, uint32_t& r1,
                                      uint32_t& r2, uint32_t& r3) {
    asm volatile("ldmatrix.sync.aligned.m8n8.x4.shared.b16 {%0,%1,%2,%3}, [%4];"
                 : "=r"(r0), "=r"(r1), "=r"(r2), "=r"(r3) : "r"(a));
}
__device__ __forceinline__ void ldsm4t(uint32_t a, uint32_t& r0, uint32_t& r1,
                                       uint32_t& r2, uint32_t& r3) {
    asm volatile("ldmatrix.sync.aligned.m8n8.x4.trans.shared.b16 {%0,%1,%2,%3}, [%4];"
                 : "=r"(r0), "=r"(r1), "=r"(r2), "=r"(r3) : "r"(a));
}
__device__ __forceinline__ void mma16816(float* c, const uint32_t* a, uint32_t b0, uint32_t b1) {
    asm volatile("mma.sync.aligned.m16n8k16.row.col.f32.f16.f16.f32 "
                 "{%0,%1,%2,%3}, {%4,%5,%6,%7}, {%8,%9}, {%0,%1,%2,%3};"
                 : "+f"(c[0]), "+f"(c[1]), "+f"(c[2]), "+f"(c[3])
                 : "r"(a[0]), "r"(a[1]), "r"(a[2]), "r"(a[3]), "r"(b0), "r"(b1));
}

// AF32: A fp32 (converted during staging). SCALE: rows *= dinv. ALPHAS: emit GAT scores.
template<int K, int SCALE, int AF32, int ALPHAS>
__global__ void __launch_bounds__(128) k_gemm_mma(const void* __restrict__ Ain,
                                                  const __half* __restrict__ W16,
                                                  __half* __restrict__ O,
                                                  const float* __restrict__ Aps,
                                                  const float* __restrict__ Apd) {
    constexpr int NKB = K / 16;
    __shared__ __align__(16) __half Ws[K * 64];
    __shared__ __align__(16) __half As[2][128 * 24];   // 48B row stride (bank-safe)

    const int tid = threadIdx.x;
    const int lane = tid & 31, w = tid >> 5;
    const int row_blk = blockIdx.x * 128;

    // stage W into smem, XOR-swizzled 16B units: unit(kk,n16) -> kk*8 + (n16^(kk&7))
    for (int u = tid; u < K * 8; u += 128) {
        int kk = u >> 3, n16 = u & 7;
        ((uint4*)Ws)[(kk << 3) | (n16 ^ (kk & 7))] = ((const uint4*)W16)[u];
    }

    auto load_regs = [&](int kb, uint4* r) {
        int grow = row_blk + tid;
        if (AF32) {
            const float4* s = (const float4*)((const float*)Ain + (size_t)grow * K + kb * 16);
            float4 f0, f1, f2, f3;
            if (grow < NN) { f0 = s[0]; f1 = s[1]; f2 = s[2]; f3 = s[3]; }
            else { f0 = f1 = f2 = f3 = make_float4(0.f, 0.f, 0.f, 0.f); }
            r[0] = make_uint4(qpack(f0.x, f0.y), qpack(f0.z, f0.w),
                              qpack(f1.x, f1.y), qpack(f1.z, f1.w));
            r[1] = make_uint4(qpack(f2.x, f2.y), qpack(f2.z, f2.w),
                              qpack(f3.x, f3.y), qpack(f3.z, f3.w));
        } else {
            const uint4* s = (const uint4*)((const __half*)Ain + (size_t)grow * K + kb * 16);
            if (grow < NN) { r[0] = s[0]; r[1] = s[1]; }
            else { r[0] = r[1] = make_uint4(0u, 0u, 0u, 0u); }
        }
    };
    auto store_regs = [&](int buf, const uint4* r) {
        uint4* d = (uint4*)(As[buf] + tid * 24);
        d[0] = r[0]; d[1] = r[1];
    };

    uint4 rg[2];
    load_regs(0, rg);
    store_regs(0, rg);
    __syncthreads();

    float acc[2][8][4];
#pragma unroll
    for (int mi = 0; mi < 2; mi++)
#pragma unroll
        for (int ni = 0; ni < 8; ni++)
#pragma unroll
            for (int q = 0; q < 4; q++) acc[mi][ni][q] = 0.f;

    uint32_t as_u = (uint32_t)__cvta_generic_to_shared(As);
    uint32_t ws_u = (uint32_t)__cvta_generic_to_shared(Ws);

    for (int kb = 0; kb < NKB; kb++) {
        if (kb + 1 < NKB) load_regs(kb + 1, rg);
        int b = kb & 1;
        uint32_t af[2][4];
#pragma unroll
        for (int mi = 0; mi < 2; mi++) {
            uint32_t aa = as_u + b * 6144
                        + (w * 32 + mi * 16 + (lane & 15)) * 48 + ((lane >> 4) << 4);
            ldsm4(aa, af[mi][0], af[mi][1], af[mi][2], af[mi][3]);
        }
        uint32_t bf[4][4];
        int sub = lane >> 3;
        int krow = kb * 16 + ((sub & 1) << 3) + (lane & 7);
#pragma unroll
        for (int g = 0; g < 4; g++) {
            int ucol = g * 2 + (sub >> 1);
            uint32_t ba = ws_u + ((uint32_t)((krow << 3) | (ucol ^ (krow & 7))) << 4);
            ldsm4t(ba, bf[g][0], bf[g][1], bf[g][2], bf[g][3]);
        }
#pragma unroll
        for (int mi = 0; mi < 2; mi++)
#pragma unroll
            for (int ni = 0; ni < 8; ni++) {
                int g = ni >> 1, o = (ni & 1) << 1;
                mma16816(acc[mi][ni], af[mi], bf[g][o], bf[g][o + 1]);
            }
        if (kb + 1 < NKB) {
            store_regs((kb + 1) & 1, rg);
            __syncthreads();
        }
    }

    // epilogue: C frag (c0,c1)=row lane/4, cols 2*(lane%4)+{0,1}; (c2,c3)=row+8
#pragma unroll
    for (int mi = 0; mi < 2; mi++) {
        int r0 = row_blk + w * 32 + mi * 16 + (lane >> 2);
        int r1 = r0 + 8;
        float s0 = 1.f, s1 = 1.f;
        if (SCALE) {
            if (r0 < NN) s0 = g_dinv[r0];
            if (r1 < NN) s1 = g_dinv[r1];
        }
#pragma unroll
        for (int ni = 0; ni < 8; ni++) {
            int c = ni * 8 + (lane & 3) * 2;
            if (r0 < NN) {
                __half2 h = __float22half2_rn(make_float2(acc[mi][ni][0] * s0, acc[mi][ni][1] * s0));
                *(__half2*)(O + (size_t)r0 * FD + c) = h;
            }
            if (r1 < NN) {
                __half2 h = __float22half2_rn(make_float2(acc[mi][ni][2] * s1, acc[mi][ni][3] * s1));
                *(__half2*)(O + (size_t)r1 * FD + c) = h;
            }
            if (ALPHAS) {
                float2 sv = *(const float2*)&Aps[c];
                float2 dv = *(const float2*)&Apd[c];
                float vas0 = acc[mi][ni][0] * sv.x + acc[mi][ni][1] * sv.y;
                float vad0 = acc[mi][ni][0] * dv.x + acc[mi][ni][1] * dv.y;
                float vas1 = acc[mi][ni][2] * sv.x + acc[mi][ni][3] * sv.y;
                float vad1 = acc[mi][ni][2] * dv.x + acc[mi][ni][3] * dv.y;
#pragma unroll
                for (int o = 1; o < 4; o <<= 1) {
                    vas0 += __shfl_xor_sync(0xffffffffu, vas0, o);
                    vad0 += __shfl_xor_sync(0xffffffffu, vad0, o);
                    vas1 += __shfl_xor_sync(0xffffffffu, vas1, o);
                    vad1 += __shfl_xor_sync(0xffffffffu, vad1, o);
                }
                if ((lane & 3) == 0) {
                    if (r0 < NN) { g_as[r0 * NHD + ni] = vas0; g_ad[r0 * NHD + ni] = vad0; }
                    if (r1 < NN) { g_as[r1 * NHD + ni] = vas1; g_ad[r1 * NHD + ni] = vad1; }
                }
            }
        }
    }
}

// ---------------- GCN gather: warp per node, 4 edge groups x 8 feature lanes ----------------
template<int HOUT>
__global__ void __launch_bounds__(256) k_gcn_gather(const __half* __restrict__ ts,
                                                    void* __restrict__ outv,
                                                    const float* __restrict__ b,
                                                    int do_relu) {
    int warp = (blockIdx.x * blockDim.x + threadIdx.x) >> 5;
    int lane = threadIdx.x & 31;
    if (warp >= NN) return;
    int d = warp;
    int f = lane & 7, eg = lane >> 3;
    int beg = g_rowbeg[d], end = beg + g_deg[d];

    float acc[8];
#pragma unroll
    for (int i = 0; i < 8; i++) acc[i] = 0.f;
    if (eg == 0) {   // self term
        uint4 hv = *(const uint4*)(ts + (size_t)d * FD + f * 8);
        const __half2* hp = (const __half2*)&hv;
#pragma unroll
        for (int i = 0; i < 4; i++) {
            float2 v = __half22float2(hp[i]);
            acc[i * 2] += v.x; acc[i * 2 + 1] += v.y;
        }
    }

    int niter = (end - beg + 3) >> 2;
    int idx = beg + eg;
    int s = (idx < end) ? g_csrc[idx] : -1;
    for (int t = 0; t < niter; t++) {
        int idx2 = idx + 4;
        int s2 = (idx2 < end) ? g_csrc[idx2] : -1;
        if (s >= 0) {
            uint4 v = *(const uint4*)(ts + (size_t)s * FD + f * 8);
            const __half2* hp = (const __half2*)&v;
#pragma unroll
            for (int i = 0; i < 4; i++) {
                float2 w = __half22float2(hp[i]);
                acc[i * 2] += w.x; acc[i * 2 + 1] += w.y;
            }
        }
        s = s2; idx = idx2;
    }

    // merge the 4 edge groups (lanes with equal f)
#pragma unroll
    for (int i = 0; i < 8; i++) {
        acc[i] += __shfl_xor_sync(0xffffffffu, acc[i], 8);
        acc[i] += __shfl_xor_sync(0xffffffffu, acc[i], 16);
    }

    if (eg == 0) {
        float nv = g_dinv[d];
        float4 b0 = ((const float4*)b)[f * 2];
        float4 b1 = ((const float4*)b)[f * 2 + 1];
        float o[8];
        o[0] = acc[0] * nv + b0.x; o[1] = acc[1] * nv + b0.y;
        o[2] = acc[2] * nv + b0.z; o[3] = acc[3] * nv + b0.w;
        o[4] = acc[4] * nv + b1.x; o[5] = acc[5] * nv + b1.y;
        o[6] = acc[6] * nv + b1.z; o[7] = acc[7] * nv + b1.w;
        if (do_relu) {
#pragma unroll
            for (int i = 0; i < 8; i++) o[i] = fmaxf(o[i], 0.f);
        }
        if (HOUT) {
            uint4 pk = make_uint4(qpack(o[0], o[1]), qpack(o[2], o[3]),
                                  qpack(o[4], o[5]), qpack(o[6], o[7]));
            *(uint4*)((__half*)outv + (size_t)d * FD + f * 8) = pk;
        } else {
            float* op = (float*)outv + (size_t)d * FD + f * 8;
            *(float4*)op       = make_float4(o[0], o[1], o[2], o[3]);
            *(float4*)(op + 4) = make_float4(o[4], o[5], o[6], o[7]);
        }
    }
}

// ---------------- single-pass GAT: 4 edge groups x 8 lanes; lane f = head f ----------------
__global__ void __launch_bounds__(256) k_gat1(const __half* __restrict__ hg,
                                              __half* __restrict__ out,
                                              const float* __restrict__ bg) {
    int warp = (blockIdx.x * blockDim.x + threadIdx.x) >> 5;
    int lane = threadIdx.x & 31;
    if (warp >= NN) return;
    int d = warp;
    int f = lane & 7, eg = lane >> 3;
    int beg = g_rowbeg[d], end = beg + g_deg[d];

    float ad_f = g_ad[(size_t)d * NHD + f];
    float acc[8];
#pragma unroll
    for (int i = 0; i < 8; i++) acc[i] = 0.f;
    float z = 0.f;
    if (eg == 0) {   // self loop
        float as_d = g_as[(size_t)d * NHD + f];
        float ps = __expf(lrelu(as_d + ad_f));
        z = ps;
        uint4 hv = *(const uint4*)(hg + (size_t)d * FD + f * 8);
        const __half2* hp = (const __half2*)&hv;
#pragma unroll
        for (int i = 0; i < 4; i++) {
            float2 v = __half22float2(hp[i]);
            acc[i * 2] += ps * v.x; acc[i * 2 + 1] += ps * v.y;
        }
    }

    int niter = (end - beg + 3) >> 2;
    int idx = beg + eg;
    int s = (idx < end) ? g_csrc[idx] : -1;
    for (int t = 0; t < niter; t++) {
        int idx2 = idx + 4;
        int s2 = (idx2 < end) ? g_csrc[idx2] : -1;
        if (s >= 0) {
            float asv = g_as[(size_t)s * NHD + f];
            uint4 v = *(const uint4*)(hg + (size_t)s * FD + f * 8);
            float p = __expf(lrelu(asv + ad_f));
            z += p;
            const __half2* hp = (const __half2*)&v;
#pragma unroll
            for (int i = 0; i < 4; i++) {
                float2 w = __half22float2(hp[i]);
                acc[i * 2] += p * w.x; acc[i * 2 + 1] += p * w.y;
            }
        }
        s = s2; idx = idx2;
    }

    // merge the 4 edge groups
    z += __shfl_xor_sync(0xffffffffu, z, 8);
    z += __shfl_xor_sync(0xffffffffu, z, 16);
#pragma unroll
    for (int i = 0; i < 8; i++) {
        acc[i] += __shfl_xor_sync(0xffffffffu, acc[i], 8);
        acc[i] += __shfl_xor_sync(0xffffffffu, acc[i], 16);
    }

    if (eg == 0) {
        float zi = 1.0f / z;
        float4 b0 = ((const float4*)bg)[f * 2];
        float4 b1 = ((const float4*)bg)[f * 2 + 1];
        float o[8];
        o[0] = fmaxf(acc[0] * zi + b0.x, 0.f); o[1] = fmaxf(acc[1] * zi + b0.y, 0.f);
        o[2] = fmaxf(acc[2] * zi + b0.z, 0.f); o[3] = fmaxf(acc[3] * zi + b0.w, 0.f);
        o[4] = fmaxf(acc[4] * zi + b1.x, 0.f); o[5] = fmaxf(acc[5] * zi + b1.y, 0.f);
        o[6] = fmaxf(acc[6] * zi + b1.z, 0.f); o[7] = fmaxf(acc[7] * zi + b1.w, 0.f);
        uint4 pk = make_uint4(qpack(o[0], o[1]), qpack(o[2], o[3]),
                              qpack(o[4], o[5]), qpack(o[6], o[7]));
        *(uint4*)(out + (size_t)d * FD + f * 8) = pk;
    }
}

// ---------------- driver ----------------
extern "C" void kernel_launch(void* const* d_in, const int* in_sizes, int n_in,
                              void* d_out, int out_size) {
    const float* x    = (const float*)d_in[0];
    const int*   ei   = (const int*)d_in[1];
    const float* W0   = (const float*)d_in[2];
    const float* b0   = (const float*)d_in[3];
    const float* Wg   = (const float*)d_in[4];
    const float* Asrc = (const float*)d_in[5];
    const float* Adst = (const float*)d_in[6];
    const float* bg   = (const float*)d_in[7];
    const float* W2   = (const float*)d_in[8];
    const float* b2   = (const float*)d_in[9];
    const float* W3   = (const float*)d_in[10];
    const float* b3   = (const float*)d_in[11];
    const int* src = ei;
    const int* dst = ei + EE;

    __half* t16; cudaGetSymbolAddress((void**)&t16, g_t);
    __half* h16; cudaGetSymbolAddress((void**)&h16, g_h);
    __half* w16; cudaGetSymbolAddress((void**)&w16, g_w16);
    float* outp = (float*)d_out;

    const int T = 256;
    const int gN    = CDIV(NN, T);
    const int gE    = CDIV(EE, T);
    const int gGemm = CDIV(NN, 128);
    const int gWarp = CDIV(NN * 32, T);

    // ---- weight conversion (+zero) + CSR build (atomic allocation) ----
    k_w2h<<<gN, T>>>(W0, Wg, W2, W3);
    k_deg<<<gE, T>>>(dst);
    k_alloc<<<gN, T>>>();
    k_scatter<<<gE, T>>>(src, dst);

    // ---- layer 0: GCN(128->64) + relu ----
    k_gemm_mma<128, 1, 1, 0><<<gGemm, 128>>>(x, w16, t16, nullptr, nullptr);
    k_gcn_gather<1><<<gWarp, T>>>(t16, h16, b0, 1);

    // ---- layer 1: GAT(64 -> 8x8 concat) + relu; alphas fused into GEMM epilogue ----
    k_gemm_mma<64, 0, 0, 1><<<gGemm, 128>>>(h16, w16 + 8192, t16, Asrc, Adst);
    k_gat1<<<gWarp, T>>>(t16, h16, bg);

    // ---- layer 2: GCN(64->64) + relu ----
    k_gemm_mma<64, 1, 0, 0><<<gGemm, 128>>>(h16, w16 + 12288, t16, nullptr, nullptr);
    k_gcn_gather<1><<<gWarp, T>>>(t16, h16, b2, 1);

    // ---- layer 3: GCN(64->64) into d_out, no relu ----
    k_gemm_mma<64, 1, 0, 0><<<gGemm, 128>>>(h16, w16 + 16384, t16, nullptr, nullptr);
    k_gcn_gather<0><<<gWarp, T>>>(t16, outp, b3, 0);
}

// round 13
// speedup vs baseline: 1.4374x; 1.4374x over previous
#include <cuda_runtime.h>
#include <cuda_fp16.h>
#include <cstdint>

#define NN 100000
#define EE 1600000
#define FD 64
#define NHD 8
#define NB  391               // CDIV(NN,256) scan blocks
#define CDIV(a,b) (((a)+(b)-1)/(b))

// ---------------- scratch ----------------
static __device__ __align__(16) float  g_dinv[NN];
static __device__ __align__(16) __half g_t  [NN*FD];     // GEMM output (messages)
static __device__ __align__(16) __half g_h  [NN*FD];     // layer activations (fp16)
static __device__ __align__(16) __half g_w16[20480];     // W0(8192) Wg(4096) W2(4096) W3(4096)
static __device__ __align__(16) float  g_as [NN*NHD];
static __device__ __align__(16) float  g_ad [NN*NHD];
static __device__ int g_deg[NN];
static __device__ int g_rowptr[NN+1];
static __device__ int g_cursor[NN];
static __device__ int g_csrc[EE];
static __device__ int g_bsum[512];

__device__ __forceinline__ float lrelu(float x) { return x > 0.f ? x : 0.2f * x; }
__device__ __forceinline__ uint32_t qpack(float a, float b) {
    __half2 h = __float22half2_rn(make_float2(a, b));
    return *(uint32_t*)&h;
}

// ---------------- weight conversion + degree zero ----------------
__global__ void k_w2h(const float* __restrict__ W0, const float* __restrict__ Wg,
                      const float* __restrict__ W2, const float* __restrict__ W3) {
    int i = blockIdx.x * blockDim.x + threadIdx.x;
    if (i < NN) g_deg[i] = 0;
    if (i < 8192) g_w16[i] = __float2half(W0[i]);
    if (i < 4096) {
        g_w16[8192  + i] = __float2half(Wg[i]);
        g_w16[12288 + i] = __float2half(W2[i]);
        g_w16[16384 + i] = __float2half(W3[i]);
    }
}

// ---------------- CSR build (prefix-sum layout: segments in node order!) ----------------
// 4 edges per thread, independent ops for MLP.
#define EB 4
#define ESTRIDE (EE / EB)     // 400000
__global__ void k_deg(const int* __restrict__ dst) {
    int e = blockIdx.x * blockDim.x + threadIdx.x;
    if (e >= ESTRIDE) return;
#pragma unroll
    for (int j = 0; j < EB; j++)
        atomicAdd(&g_deg[dst[e + j * ESTRIDE]], 1);
}
__global__ void __launch_bounds__(256) k_scan1() {
    int i = blockIdx.x * 256 + threadIdx.x;
    int v = (i < NN) ? g_deg[i] : 0;
    if (i < NN) g_dinv[i] = rsqrtf((float)(v + 1));
    int lane = threadIdx.x & 31, wid = threadIdx.x >> 5;
    int x = v;
#pragma unroll
    for (int o = 1; o < 32; o <<= 1) { int y = __shfl_up_sync(~0u, x, o); if (lane >= o) x += y; }
    __shared__ int ws[8];
    if (lane == 31) ws[wid] = x;
    __syncthreads();
    if (wid == 0) {
        int t = (lane < 8) ? ws[lane] : 0;
#pragma unroll
        for (int o = 1; o < 8; o <<= 1) { int y = __shfl_up_sync(~0u, t, o); if (lane >= o) t += y; }
        if (lane < 8) ws[lane] = t;
    }
    __syncthreads();
    int base = wid > 0 ? ws[wid - 1] : 0;
    int incl = x + base;
    if (i < NN) g_rowptr[i] = incl - v;
    if (threadIdx.x == 255) g_bsum[blockIdx.x] = incl;
}
__global__ void __launch_bounds__(512) k_scan2() {
    int i = threadIdx.x;
    int v = (i < NB) ? g_bsum[i] : 0;
    int lane = i & 31, wid = i >> 5;
    int x = v;
#pragma unroll
    for (int o = 1; o < 32; o <<= 1) { int y = __shfl_up_sync(~0u, x, o); if (lane >= o) x += y; }
    __shared__ int ws[16];
    if (lane == 31) ws[wid] = x;
    __syncthreads();
    if (wid == 0) {
        int t = (lane < 16) ? ws[lane] : 0;
#pragma unroll
        for (int o = 1; o < 16; o <<= 1) { int y = __shfl_up_sync(~0u, t, o); if (lane >= o) t += y; }
        if (lane < 16) ws[lane] = t;
    }
    __syncthreads();
    int base = wid > 0 ? ws[wid - 1] : 0;
    if (i < NB) g_bsum[i] = x + base - v;
}
__global__ void k_scan3() {
    int i = blockIdx.x * blockDim.x + threadIdx.x;
    if (i < NN) {
        int r = g_rowptr[i] + g_bsum[i >> 8];
        g_rowptr[i] = r;
        g_cursor[i] = r;
    }
    if (i == 0) g_rowptr[NN] = EE;
}
__global__ void k_scatter(const int* __restrict__ src, const int* __restrict__ dst) {
    int e = blockIdx.x * blockDim.x + threadIdx.x;
    if (e >= ESTRIDE) return;
    int sv[EB], pos[EB];
#pragma unroll
    for (int j = 0; j < EB; j++) {
        int ee = e + j * ESTRIDE;
        sv[j] = src[ee];
        pos[j] = atomicAdd(&g_cursor[dst[ee]], 1);
    }
#pragma unroll
    for (int j = 0; j < EB; j++)
        g_csrc[pos[j]] = sv[j];
}

// ---------------- tensor-core GEMM: [NN,K]x[K,64] -> fp16 [NN,64] ----------------
__device__ __forceinline__ void ldsm4(uint32_t a, uint32_t& r0, uint32_t& r1,
                                      uint32_t& r2, uint32_t& r3) {
    asm volatile("ldmatrix.sync.aligned.m8n8.x4.shared.b16 {%0,%1,%2,%3}, [%4];"
                 : "=r"(r0), "=r"(r1), "=r"(r2), "=r"(r3) : "r"(a));
}
__device__ __forceinline__ void ldsm4t(uint32_t a, uint32_t& r0, uint32_t& r1,
                                       uint32_t& r2, uint32_t& r3) {
    asm volatile("ldmatrix.sync.aligned.m8n8.x4.trans.shared.b16 {%0,%1,%2,%3}, [%4];"
                 : "=r"(r0), "=r"(r1), "=r"(r2), "=r"(r3) : "r"(a));
}
__device__ __forceinline__ void mma16816(float* c, const uint32_t* a, uint32_t b0, uint32_t b1) {
    asm volatile("mma.sync.aligned.m16n8k16.row.col.f32.f16.f16.f32 "
                 "{%0,%1,%2,%3}, {%4,%5,%6,%7}, {%8,%9}, {%0,%1,%2,%3};"
                 : "+f"(c[0]), "+f"(c[1]), "+f"(c[2]), "+f"(c[3])
                 : "r"(a[0]), "r"(a[1]), "r"(a[2]), "r"(a[3]), "r"(b0), "r"(b1));
}

// AF32: A fp32 (converted during staging). SCALE: rows *= dinv. ALPHAS: emit GAT scores.
template<int K, int SCALE, int AF32, int ALPHAS>
__global__ void __launch_bounds__(128) k_gemm_mma(const void* __restrict__ Ain,
                                                  const __half* __restrict__ W16,
                                                  __half* __restrict__ O,
                                                  const float* __restrict__ Aps,
                                                  const float* __restrict__ Apd) {
    constexpr int NKB = K / 16;
    __shared__ __align__(16) __half Ws[K * 64];
    __shared__ __align__(16) __half As[2][128 * 24];   // 48B row stride (bank-safe)

    const int tid = threadIdx.x;
    const int lane = tid & 31, w = tid >> 5;
    const int row_blk = blockIdx.x * 128;

    // stage W into smem, XOR-swizzled 16B units: unit(kk,n16) -> kk*8 + (n16^(kk&7))
    for (int u = tid; u < K * 8; u += 128) {
        int kk = u >> 3, n16 = u & 7;
        ((uint4*)Ws)[(kk << 3) | (n16 ^ (kk & 7))] = ((const uint4*)W16)[u];
    }

    auto load_regs = [&](int kb, uint4* r) {
        int grow = row_blk + tid;
        if (AF32) {
            const float4* s = (const float4*)((const float*)Ain + (size_t)grow * K + kb * 16);
            float4 f0, f1, f2, f3;
            if (grow < NN) { f0 = s[0]; f1 = s[1]; f2 = s[2]; f3 = s[3]; }
            else { f0 = f1 = f2 = f3 = make_float4(0.f, 0.f, 0.f, 0.f); }
            r[0] = make_uint4(qpack(f0.x, f0.y), qpack(f0.z, f0.w),
                              qpack(f1.x, f1.y), qpack(f1.z, f1.w));
            r[1] = make_uint4(qpack(f2.x, f2.y), qpack(f2.z, f2.w),
                              qpack(f3.x, f3.y), qpack(f3.z, f3.w));
        } else {
            const uint4* s = (const uint4*)((const __half*)Ain + (size_t)grow * K + kb * 16);
            if (grow < NN) { r[0] = s[0]; r[1] = s[1]; }
            else { r[0] = r[1] = make_uint4(0u, 0u, 0u, 0u); }
        }
    };
    auto store_regs = [&](int buf, const uint4* r) {
        uint4* d = (uint4*)(As[buf] + tid * 24);
        d[0] = r[0]; d[1] = r[1];
    };

    uint4 rg[2];
    load_regs(0, rg);
    store_regs(0, rg);
    __syncthreads();

    float acc[2][8][4];
#pragma unroll
    for (int mi = 0; mi < 2; mi++)
#pragma unroll
        for (int ni = 0; ni < 8; ni++)
#pragma unroll
            for (int q = 0; q < 4; q++) acc[mi][ni][q] = 0.f;

    uint32_t as_u = (uint32_t)__cvta_generic_to_shared(As);
    uint32_t ws_u = (uint32_t)__cvta_generic_to_shared(Ws);

    for (int kb = 0; kb < NKB; kb++) {
        if (kb + 1 < NKB) load_regs(kb + 1, rg);
        int b = kb & 1;
        uint32_t af[2][4];
#pragma unroll
        for (int mi = 0; mi < 2; mi++) {
            uint32_t aa = as_u + b * 6144
                        + (w * 32 + mi * 16 + (lane & 15)) * 48 + ((lane >> 4) << 4);
            ldsm4(aa, af[mi][0], af[mi][1], af[mi][2], af[mi][3]);
        }
        uint32_t bf[4][4];
        int sub = lane >> 3;
        int krow = kb * 16 + ((sub & 1) << 3) + (lane & 7);
#pragma unroll
        for (int g = 0; g < 4; g++) {
            int ucol = g * 2 + (sub >> 1);
            uint32_t ba = ws_u + ((uint32_t)((krow << 3) | (ucol ^ (krow & 7))) << 4);
            ldsm4t(ba, bf[g][0], bf[g][1], bf[g][2], bf[g][3]);
        }
#pragma unroll
        for (int mi = 0; mi < 2; mi++)
#pragma unroll
            for (int ni = 0; ni < 8; ni++) {
                int g = ni >> 1, o = (ni & 1) << 1;
                mma16816(acc[mi][ni], af[mi], bf[g][o], bf[g][o + 1]);
            }
        if (kb + 1 < NKB) {
            store_regs((kb + 1) & 1, rg);
            __syncthreads();
        }
    }

    // epilogue: C frag (c0,c1)=row lane/4, cols 2*(lane%4)+{0,1}; (c2,c3)=row+8
#pragma unroll
    for (int mi = 0; mi < 2; mi++) {
        int r0 = row_blk + w * 32 + mi * 16 + (lane >> 2);
        int r1 = r0 + 8;
        float s0 = 1.f, s1 = 1.f;
        if (SCALE) {
            if (r0 < NN) s0 = g_dinv[r0];
            if (r1 < NN) s1 = g_dinv[r1];
        }
#pragma unroll
        for (int ni = 0; ni < 8; ni++) {
            int c = ni * 8 + (lane & 3) * 2;
            if (r0 < NN) {
                __half2 h = __float22half2_rn(make_float2(acc[mi][ni][0] * s0, acc[mi][ni][1] * s0));
                *(__half2*)(O + (size_t)r0 * FD + c) = h;
            }
            if (r1 < NN) {
                __half2 h = __float22half2_rn(make_float2(acc[mi][ni][2] * s1, acc[mi][ni][3] * s1));
                *(__half2*)(O + (size_t)r1 * FD + c) = h;
            }
            if (ALPHAS) {
                float2 sv = *(const float2*)&Aps[c];
                float2 dv = *(const float2*)&Apd[c];
                float vas0 = acc[mi][ni][0] * sv.x + acc[mi][ni][1] * sv.y;
                float vad0 = acc[mi][ni][0] * dv.x + acc[mi][ni][1] * dv.y;
                float vas1 = acc[mi][ni][2] * sv.x + acc[mi][ni][3] * sv.y;
                float vad1 = acc[mi][ni][2] * dv.x + acc[mi][ni][3] * dv.y;
#pragma unroll
                for (int o = 1; o < 4; o <<= 1) {
                    vas0 += __shfl_xor_sync(0xffffffffu, vas0, o);
                    vad0 += __shfl_xor_sync(0xffffffffu, vad0, o);
                    vas1 += __shfl_xor_sync(0xffffffffu, vas1, o);
                    vad1 += __shfl_xor_sync(0xffffffffu, vad1, o);
                }
                if ((lane & 3) == 0) {
                    if (r0 < NN) { g_as[r0 * NHD + ni] = vas0; g_ad[r0 * NHD + ni] = vad0; }
                    if (r1 < NN) { g_as[r1 * NHD + ni] = vas1; g_ad[r1 * NHD + ni] = vad1; }
                }
            }
        }
    }
}

// ---------------- GCN gather: warp per node, 4 edge groups x 8 feature lanes ----------------
template<int HOUT>
__global__ void __launch_bounds__(256) k_gcn_gather(const __half* __restrict__ ts,
                                                    void* __restrict__ outv,
                                                    const float* __restrict__ b,
                                                    int do_relu) {
    int warp = (blockIdx.x * blockDim.x + threadIdx.x) >> 5;
    int lane = threadIdx.x & 31;
    if (warp >= NN) return;
    int d = warp;
    int f = lane & 7, eg = lane >> 3;
    int beg = g_rowptr[d], end = g_rowptr[d + 1];

    float acc[8];
#pragma unroll
    for (int i = 0; i < 8; i++) acc[i] = 0.f;
    if (eg == 0) {   // self term
        uint4 hv = *(const uint4*)(ts + (size_t)d * FD + f * 8);
        const __half2* hp = (const __half2*)&hv;
#pragma unroll
        for (int i = 0; i < 4; i++) {
            float2 v = __half22float2(hp[i]);
            acc[i * 2] += v.x; acc[i * 2 + 1] += v.y;
        }
    }

    int niter = (end - beg + 3) >> 2;
    int idx = beg + eg;
    int s = (idx < end) ? g_csrc[idx] : -1;
    for (int t = 0; t < niter; t++) {
        int idx2 = idx + 4;
        int s2 = (idx2 < end) ? g_csrc[idx2] : -1;
        if (s >= 0) {
            uint4 v = *(const uint4*)(ts + (size_t)s * FD + f * 8);
            const __half2* hp = (const __half2*)&v;
#pragma unroll
            for (int i = 0; i < 4; i++) {
                float2 w = __half22float2(hp[i]);
                acc[i * 2] += w.x; acc[i * 2 + 1] += w.y;
            }
        }
        s = s2; idx = idx2;
    }

    // merge the 4 edge groups (lanes with equal f)
#pragma unroll
    for (int i = 0; i < 8; i++) {
        acc[i] += __shfl_xor_sync(0xffffffffu, acc[i], 8);
        acc[i] += __shfl_xor_sync(0xffffffffu, acc[i], 16);
    }

    if (eg == 0) {
        float nv = g_dinv[d];
        float4 b0 = ((const float4*)b)[f * 2];
        float4 b1 = ((const float4*)b)[f * 2 + 1];
        float o[8];
        o[0] = acc[0] * nv + b0.x; o[1] = acc[1] * nv + b0.y;
        o[2] = acc[2] * nv + b0.z; o[3] = acc[3] * nv + b0.w;
        o[4] = acc[4] * nv + b1.x; o[5] = acc[5] * nv + b1.y;
        o[6] = acc[6] * nv + b1.z; o[7] = acc[7] * nv + b1.w;
        if (do_relu) {
#pragma unroll
            for (int i = 0; i < 8; i++) o[i] = fmaxf(o[i], 0.f);
        }
        if (HOUT) {
            uint4 pk = make_uint4(qpack(o[0], o[1]), qpack(o[2], o[3]),
                                  qpack(o[4], o[5]), qpack(o[6], o[7]));
            *(uint4*)((__half*)outv + (size_t)d * FD + f * 8) = pk;
        } else {
            float* op = (float*)outv + (size_t)d * FD + f * 8;
            *(float4*)op       = make_float4(o[0], o[1], o[2], o[3]);
            *(float4*)(op + 4) = make_float4(o[4], o[5], o[6], o[7]);
        }
    }
}

// ---------------- single-pass GAT: 4 edge groups x 8 lanes; lane f = head f ----------------
__global__ void __launch_bounds__(256) k_gat1(const __half* __restrict__ hg,
                                              __half* __restrict__ out,
                                              const float* __restrict__ bg) {
    int warp = (blockIdx.x * blockDim.x + threadIdx.x) >> 5;
    int lane = threadIdx.x & 31;
    if (warp >= NN) return;
    int d = warp;
    int f = lane & 7, eg = lane >> 3;
    int beg = g_rowptr[d], end = g_rowptr[d + 1];

    float ad_f = g_ad[(size_t)d * NHD + f];
    float acc[8];
#pragma unroll
    for (int i = 0; i < 8; i++) acc[i] = 0.f;
    float z = 0.f;
    if (eg == 0) {   // self loop
        float as_d = g_as[(size_t)d * NHD + f];
        float ps = __expf(lrelu(as_d + ad_f));
        z = ps;
        uint4 hv = *(const uint4*)(hg + (size_t)d * FD + f * 8);
        const __half2* hp = (const __half2*)&hv;
#pragma unroll
        for (int i = 0; i < 4; i++) {
            float2 v = __half22float2(hp[i]);
            acc[i * 2] += ps * v.x; acc[i * 2 + 1] += ps * v.y;
        }
    }

    int niter = (end - beg + 3) >> 2;
    int idx = beg + eg;
    int s = (idx < end) ? g_csrc[idx] : -1;
    for (int t = 0; t < niter; t++) {
        int idx2 = idx + 4;
        int s2 = (idx2 < end) ? g_csrc[idx2] : -1;
        if (s >= 0) {
            float asv = g_as[(size_t)s * NHD + f];
            uint4 v = *(const uint4*)(hg + (size_t)s * FD + f * 8);
            float p = __expf(lrelu(asv + ad_f));
            z += p;
            const __half2* hp = (const __half2*)&v;
#pragma unroll
            for (int i = 0; i < 4; i++) {
                float2 w = __half22float2(hp[i]);
                acc[i * 2] += p * w.x; acc[i * 2 + 1] += p * w.y;
            }
        }
        s = s2; idx = idx2;
    }

    // merge the 4 edge groups
    z += __shfl_xor_sync(0xffffffffu, z, 8);
    z += __shfl_xor_sync(0xffffffffu, z, 16);
#pragma unroll
    for (int i = 0; i < 8; i++) {
        acc[i] += __shfl_xor_sync(0xffffffffu, acc[i], 8);
        acc[i] += __shfl_xor_sync(0xffffffffu, acc[i], 16);
    }

    if (eg == 0) {
        float zi = 1.0f / z;
        float4 b0 = ((const float4*)bg)[f * 2];
        float4 b1 = ((const float4*)bg)[f * 2 + 1];
        float o[8];
        o[0] = fmaxf(acc[0] * zi + b0.x, 0.f); o[1] = fmaxf(acc[1] * zi + b0.y, 0.f);
        o[2] = fmaxf(acc[2] * zi + b0.z, 0.f); o[3] = fmaxf(acc[3] * zi + b0.w, 0.f);
        o[4] = fmaxf(acc[4] * zi + b1.x, 0.f); o[5] = fmaxf(acc[5] * zi + b1.y, 0.f);
        o[6] = fmaxf(acc[6] * zi + b1.z, 0.f); o[7] = fmaxf(acc[7] * zi + b1.w, 0.f);
        uint4 pk = make_uint4(qpack(o[0], o[1]), qpack(o[2], o[3]),
                              qpack(o[4], o[5]), qpack(o[6], o[7]));
        *(uint4*)(out + (size_t)d * FD + f * 8) = pk;
    }
}

// ---------------- driver ----------------
extern "C" void kernel_launch(void* const* d_in, const int* in_sizes, int n_in,
                              void* d_out, int out_size) {
    const float* x    = (const float*)d_in[0];
    const int*   ei   = (const int*)d_in[1];
    const float* W0   = (const float*)d_in[2];
    const float* b0   = (const float*)d_in[3];
    const float* Wg   = (const float*)d_in[4];
    const float* Asrc = (const float*)d_in[5];
    const float* Adst = (const float*)d_in[6];
    const float* bg   = (const float*)d_in[7];
    const float* W2   = (const float*)d_in[8];
    const float* b2   = (const float*)d_in[9];
    const float* W3   = (const float*)d_in[10];
    const float* b3   = (const float*)d_in[11];
    const int* src = ei;
    const int* dst = ei + EE;

    __half* t16; cudaGetSymbolAddress((void**)&t16, g_t);
    __half* h16; cudaGetSymbolAddress((void**)&h16, g_h);
    __half* w16; cudaGetSymbolAddress((void**)&w16, g_w16);
    float* outp = (float*)d_out;

    const int T = 256;
    const int gN    = CDIV(NN, T);
    const int gE4   = CDIV(ESTRIDE, T);
    const int gGemm = CDIV(NN, 128);
    const int gWarp = CDIV(NN * 32, T);

    // ---- weight conversion (+deg zero) + CSR build (prefix-sum layout) ----
    k_w2h<<<gN, T>>>(W0, Wg, W2, W3);
    k_deg<<<gE4, T>>>(dst);
    k_scan1<<<NB, 256>>>();
    k_scan2<<<1, 512>>>();
    k_scan3<<<gN, T>>>();
    k_scatter<<<gE4, T>>>(src, dst);

    // ---- layer 0: GCN(128->64) + relu ----
    k_gemm_mma<128, 1, 1, 0><<<gGemm, 128>>>(x, w16, t16, nullptr, nullptr);
    k_gcn_gather<1><<<gWarp, T>>>(t16, h16, b0, 1);

    // ---- layer 1: GAT(64 -> 8x8 concat) + relu; alphas fused into GEMM epilogue ----
    k_gemm_mma<64, 0, 0, 1><<<gGemm, 128>>>(h16, w16 + 8192, t16, Asrc, Adst);
    k_gat1<<<gWarp, T>>>(t16, h16, bg);

    // ---- layer 2: GCN(64->64) + relu ----
    k_gemm_mma<64, 1, 0, 0><<<gGemm, 128>>>(h16, w16 + 12288, t16, nullptr, nullptr);
    k_gcn_gather<1><<<gWarp, T>>>(t16, h16, b2, 1);

    // ---- layer 3: GCN(64->64) into d_out, no relu ----
    k_gemm_mma<64, 1, 0, 0><<<gGemm, 128>>>(h16, w16 + 16384, t16, nullptr, nullptr);
    k_gcn_gather<0><<<gWarp, T>>>(t16, outp, b3, 0);
}

// round 14
// speedup vs baseline: 1.4941x; 1.0394x over previous
#include <cuda_runtime.h>
#include <cuda_fp16.h>
#include <cstdint>

#define NN 100000
#define EE 1600000
#define FD 64
#define NHD 8
#define NB  391               // CDIV(NN,256) scan blocks
#define CDIV(a,b) (((a)+(b)-1)/(b))

// ---------------- scratch ----------------
static __device__ __align__(16) float  g_dinv[NN];
static __device__ __align__(16) __half g_t  [NN*FD];     // GEMM output (messages)
static __device__ __align__(16) __half g_h  [NN*FD];     // layer activations (fp16)
static __device__ __align__(16) __half g_w16[20480];     // W0(8192) Wg(4096) W2(4096) W3(4096)
static __device__ __align__(16) float  g_as [NN*NHD];
static __device__ __align__(16) float  g_ad [NN*NHD];
static __device__ int g_deg[NN];
static __device__ int g_rowptr[NN+1];
static __device__ int g_cursor[NN];
static __device__ int g_csrc[EE];
static __device__ unsigned long long g_stat[512];        // lookback scan status

__device__ __forceinline__ float lrelu(float x) { return x > 0.f ? x : 0.2f * x; }
__device__ __forceinline__ uint32_t qpack(float a, float b) {
    __half2 h = __float22half2_rn(make_float2(a, b));
    return *(uint32_t*)&h;
}

// ---------------- weight conversion + zero (deg, scan status) ----------------
__global__ void k_w2h(const float* __restrict__ W0, const float* __restrict__ Wg,
                      const float* __restrict__ W2, const float* __restrict__ W3) {
    int i = blockIdx.x * blockDim.x + threadIdx.x;
    if (i < NN) g_deg[i] = 0;
    if (i < 512) g_stat[i] = 0ULL;
    if (i < 8192) g_w16[i] = __float2half(W0[i]);
    if (i < 4096) {
        g_w16[8192  + i] = __float2half(Wg[i]);
        g_w16[12288 + i] = __float2half(W2[i]);
        g_w16[16384 + i] = __float2half(W3[i]);
    }
}

// ---------------- CSR build (prefix-sum layout, single-pass lookback scan) ----------------
#define EB 4
#define ESTRIDE (EE / EB)     // 400000
__global__ void k_deg(const int* __restrict__ dst) {
    int e = blockIdx.x * blockDim.x + threadIdx.x;
    if (e >= ESTRIDE) return;
#pragma unroll
    for (int j = 0; j < EB; j++)
        atomicAdd(&g_deg[dst[e + j * ESTRIDE]], 1);
}
// single-pass scan with decoupled lookback; also computes dinv. All NB blocks co-resident.
__global__ void __launch_bounds__(256) k_scan_lb() {
    int b = blockIdx.x;
    int i = b * 256 + threadIdx.x;
    int v = (i < NN) ? g_deg[i] : 0;
    if (i < NN) g_dinv[i] = rsqrtf((float)(v + 1));
    int lane = threadIdx.x & 31, wid = threadIdx.x >> 5;
    int x = v;
#pragma unroll
    for (int o = 1; o < 32; o <<= 1) { int y = __shfl_up_sync(~0u, x, o); if (lane >= o) x += y; }
    __shared__ int ws[8];
    if (lane == 31) ws[wid] = x;
    __syncthreads();
    if (wid == 0) {
        int t = (lane < 8) ? ws[lane] : 0;
#pragma unroll
        for (int o = 1; o < 8; o <<= 1) { int y = __shfl_up_sync(~0u, t, o); if (lane >= o) t += y; }
        if (lane < 8) ws[lane] = t;
    }
    __syncthreads();
    int base = wid > 0 ? ws[wid - 1] : 0;
    int incl = x + base;          // inclusive prefix within block
    int bt = ws[7];               // block total
    __shared__ int s_pref;
    if (threadIdx.x == 0) {
        if (b == 0) {
            atomicExch(&g_stat[0], ((unsigned long long)bt << 2) | 2ULL);
            s_pref = 0;
        } else {
            atomicExch(&g_stat[b], ((unsigned long long)bt << 2) | 1ULL);
            int run = 0, pb = b - 1;
            while (true) {
                unsigned long long st = *(volatile unsigned long long*)&g_stat[pb];
                unsigned sflag = (unsigned)(st & 3ULL);
                if (sflag == 0) continue;
                run += (int)(st >> 2);
                if (sflag == 2) break;
                pb--;
            }
            s_pref = run;
            atomicExch(&g_stat[b], ((unsigned long long)(run + bt) << 2) | 2ULL);
        }
    }
    __syncthreads();
    int ex = s_pref + incl - v;   // exclusive global prefix
    if (i < NN) { g_rowptr[i] = ex; g_cursor[i] = ex; }
    if (i == 0) g_rowptr[NN] = EE;
}
__global__ void k_scatter(const int* __restrict__ src, const int* __restrict__ dst) {
    int e = blockIdx.x * blockDim.x + threadIdx.x;
    if (e >= ESTRIDE) return;
    int sv[EB], pos[EB];
#pragma unroll
    for (int j = 0; j < EB; j++) {
        int ee = e + j * ESTRIDE;
        sv[j] = src[ee];
        pos[j] = atomicAdd(&g_cursor[dst[ee]], 1);
    }
#pragma unroll
    for (int j = 0; j < EB; j++)
        g_csrc[pos[j]] = sv[j];
}

// ---------------- tensor-core GEMM: [NN,K]x[K,64] -> fp16 [NN,64] ----------------
__device__ __forceinline__ void ldsm4(uint32_t a, uint32_t& r0, uint32_t& r1,
                                      uint32_t& r2, uint32_t& r3) {
    asm volatile("ldmatrix.sync.aligned.m8n8.x4.shared.b16 {%0,%1,%2,%3}, [%4];"
                 : "=r"(r0), "=r"(r1), "=r"(r2), "=r"(r3) : "r"(a));
}
__device__ __forceinline__ void ldsm4t(uint32_t a, uint32_t& r0, uint32_t& r1,
                                       uint32_t& r2, uint32_t& r3) {
    asm volatile("ldmatrix.sync.aligned.m8n8.x4.trans.shared.b16 {%0,%1,%2,%3}, [%4];"
                 : "=r"(r0), "=r"(r1), "=r"(r2), "=r"(r3) : "r"(a));
}
__device__ __forceinline__ void mma16816(float* c, const uint32_t* a, uint32_t b0, uint32_t b1) {
    asm volatile("mma.sync.aligned.m16n8k16.row.col.f32.f16.f16.f32 "
                 "{%0,%1,%2,%3}, {%4,%5,%6,%7}, {%8,%9}, {%0,%1,%2,%3};"
                 : "+f"(c[0]), "+f"(c[1]), "+f"(c[2]), "+f"(c[3])
                 : "r"(a[0]), "r"(a[1]), "r"(a[2]), "r"(a[3]), "r"(b0), "r"(b1));
}

// AF32: A fp32 (converted during staging). SCALE: rows *= dinv. ALPHAS: emit GAT scores.
template<int K, int SCALE, int AF32, int ALPHAS>
__global__ void __launch_bounds__(128) k_gemm_mma(const void* __restrict__ Ain,
                                                  const __half* __restrict__ W16,
                                                  __half* __restrict__ O,
                                                  const float* __restrict__ Aps,
                                                  const float* __restrict__ Apd) {
    constexpr int NKB = K / 16;
    __shared__ __align__(16) __half Ws[K * 64];
    __shared__ __align__(16) __half As[2][128 * 24];   // 48B row stride (bank-safe)

    const int tid = threadIdx.x;
    const int lane = tid & 31, w = tid >> 5;
    const int row_blk = blockIdx.x * 128;

    // stage W into smem, XOR-swizzled 16B units: unit(kk,n16) -> kk*8 + (n16^(kk&7))
    for (int u = tid; u < K * 8; u += 128) {
        int kk = u >> 3, n16 = u & 7;
        ((uint4*)Ws)[(kk << 3) | (n16 ^ (kk & 7))] = ((const uint4*)W16)[u];
    }

    auto load_regs = [&](int kb, uint4* r) {
        int grow = row_blk + tid;
        if (AF32) {
            const float4* s = (const float4*)((const float*)Ain + (size_t)grow * K + kb * 16);
            float4 f0, f1, f2, f3;
            if (grow < NN) { f0 = s[0]; f1 = s[1]; f2 = s[2]; f3 = s[3]; }
            else { f0 = f1 = f2 = f3 = make_float4(0.f, 0.f, 0.f, 0.f); }
            r[0] = make_uint4(qpack(f0.x, f0.y), qpack(f0.z, f0.w),
                              qpack(f1.x, f1.y), qpack(f1.z, f1.w));
            r[1] = make_uint4(qpack(f2.x, f2.y), qpack(f2.z, f2.w),
                              qpack(f3.x, f3.y), qpack(f3.z, f3.w));
        } else {
            const uint4* s = (const uint4*)((const __half*)Ain + (size_t)grow * K + kb * 16);
            if (grow < NN) { r[0] = s[0]; r[1] = s[1]; }
            else { r[0] = r[1] = make_uint4(0u, 0u, 0u, 0u); }
        }
    };
    auto store_regs = [&](int buf, const uint4* r) {
        uint4* d = (uint4*)(As[buf] + tid * 24);
        d[0] = r[0]; d[1] = r[1];
    };

    uint4 rg[2];
    load_regs(0, rg);
    store_regs(0, rg);
    __syncthreads();

    float acc[2][8][4];
#pragma unroll
    for (int mi = 0; mi < 2; mi++)
#pragma unroll
        for (int ni = 0; ni < 8; ni++)
#pragma unroll
            for (int q = 0; q < 4; q++) acc[mi][ni][q] = 0.f;

    uint32_t as_u = (uint32_t)__cvta_generic_to_shared(As);
    uint32_t ws_u = (uint32_t)__cvta_generic_to_shared(Ws);

    for (int kb = 0; kb < NKB; kb++) {
        if (kb + 1 < NKB) load_regs(kb + 1, rg);
        int b = kb & 1;
        uint32_t af[2][4];
#pragma unroll
        for (int mi = 0; mi < 2; mi++) {
            uint32_t aa = as_u + b * 6144
                        + (w * 32 + mi * 16 + (lane & 15)) * 48 + ((lane >> 4) << 4);
            ldsm4(aa, af[mi][0], af[mi][1], af[mi][2], af[mi][3]);
        }
        uint32_t bf[4][4];
        int sub = lane >> 3;
        int krow = kb * 16 + ((sub & 1) << 3) + (lane & 7);
#pragma unroll
        for (int g = 0; g < 4; g++) {
            int ucol = g * 2 + (sub >> 1);
            uint32_t ba = ws_u + ((uint32_t)((krow << 3) | (ucol ^ (krow & 7))) << 4);
            ldsm4t(ba, bf[g][0], bf[g][1], bf[g][2], bf[g][3]);
        }
#pragma unroll
        for (int mi = 0; mi < 2; mi++)
#pragma unroll
            for (int ni = 0; ni < 8; ni++) {
                int g = ni >> 1, o = (ni & 1) << 1;
                mma16816(acc[mi][ni], af[mi], bf[g][o], bf[g][o + 1]);
            }
        if (kb + 1 < NKB) {
            store_regs((kb + 1) & 1, rg);
            __syncthreads();
        }
    }

    // epilogue: C frag (c0,c1)=row lane/4, cols 2*(lane%4)+{0,1}; (c2,c3)=row+8
#pragma unroll
    for (int mi = 0; mi < 2; mi++) {
        int r0 = row_blk + w * 32 + mi * 16 + (lane >> 2);
        int r1 = r0 + 8;
        float s0 = 1.f, s1 = 1.f;
        if (SCALE) {
            if (r0 < NN) s0 = g_dinv[r0];
            if (r1 < NN) s1 = g_dinv[r1];
        }
#pragma unroll
        for (int ni = 0; ni < 8; ni++) {
            int c = ni * 8 + (lane & 3) * 2;
            if (r0 < NN) {
                __half2 h = __float22half2_rn(make_float2(acc[mi][ni][0] * s0, acc[mi][ni][1] * s0));
                *(__half2*)(O + (size_t)r0 * FD + c) = h;
            }
            if (r1 < NN) {
                __half2 h = __float22half2_rn(make_float2(acc[mi][ni][2] * s1, acc[mi][ni][3] * s1));
                *(__half2*)(O + (size_t)r1 * FD + c) = h;
            }
            if (ALPHAS) {
                float2 sv = *(const float2*)&Aps[c];
                float2 dv = *(const float2*)&Apd[c];
                float vas0 = acc[mi][ni][0] * sv.x + acc[mi][ni][1] * sv.y;
                float vad0 = acc[mi][ni][0] * dv.x + acc[mi][ni][1] * dv.y;
                float vas1 = acc[mi][ni][2] * sv.x + acc[mi][ni][3] * sv.y;
                float vad1 = acc[mi][ni][2] * dv.x + acc[mi][ni][3] * dv.y;
#pragma unroll
                for (int o = 1; o < 4; o <<= 1) {
                    vas0 += __shfl_xor_sync(0xffffffffu, vas0, o);
                    vad0 += __shfl_xor_sync(0xffffffffu, vad0, o);
                    vas1 += __shfl_xor_sync(0xffffffffu, vas1, o);
                    vad1 += __shfl_xor_sync(0xffffffffu, vad1, o);
                }
                if ((lane & 3) == 0) {
                    if (r0 < NN) { g_as[r0 * NHD + ni] = vas0; g_ad[r0 * NHD + ni] = vad0; }
                    if (r1 < NN) { g_as[r1 * NHD + ni] = vas1; g_ad[r1 * NHD + ni] = vad1; }
                }
            }
        }
    }
}

// ---------------- GCN gather: warp per node, 4 edge groups x 8 feature lanes ----------------
// SRCSCALE: messages are unscaled; apply dinv[s] per edge (and dinv[d] on self term).
template<int HOUT, int SRCSCALE>
__global__ void __launch_bounds__(256) k_gcn_gather(const __half* __restrict__ ts,
                                                    void* __restrict__ outv,
                                                    const float* __restrict__ b,
                                                    int do_relu) {
    int warp = (blockIdx.x * blockDim.x + threadIdx.x) >> 5;
    int lane = threadIdx.x & 31;
    if (warp >= NN) return;
    int d = warp;
    int f = lane & 7, eg = lane >> 3;
    int beg = g_rowptr[d], end = g_rowptr[d + 1];
    float nv = g_dinv[d];

    float acc[8];
#pragma unroll
    for (int i = 0; i < 8; i++) acc[i] = 0.f;
    if (eg == 0) {   // self term
        float sd = SRCSCALE ? nv : 1.f;
        uint4 hv = *(const uint4*)(ts + (size_t)d * FD + f * 8);
        const __half2* hp = (const __half2*)&hv;
#pragma unroll
        for (int i = 0; i < 4; i++) {
            float2 v = __half22float2(hp[i]);
            acc[i * 2] += sd * v.x; acc[i * 2 + 1] += sd * v.y;
        }
    }

    int niter = (end - beg + 3) >> 2;
    int idx = beg + eg;
    int s = (idx < end) ? g_csrc[idx] : -1;
    for (int t = 0; t < niter; t++) {
        int idx2 = idx + 4;
        int s2 = (idx2 < end) ? g_csrc[idx2] : -1;
        if (s >= 0) {
            float sd = SRCSCALE ? g_dinv[s] : 1.f;
            uint4 v = *(const uint4*)(ts + (size_t)s * FD + f * 8);
            const __half2* hp = (const __half2*)&v;
#pragma unroll
            for (int i = 0; i < 4; i++) {
                float2 w = __half22float2(hp[i]);
                acc[i * 2] += sd * w.x; acc[i * 2 + 1] += sd * w.y;
            }
        }
        s = s2; idx = idx2;
    }

    // merge the 4 edge groups (lanes with equal f)
#pragma unroll
    for (int i = 0; i < 8; i++) {
        acc[i] += __shfl_xor_sync(0xffffffffu, acc[i], 8);
        acc[i] += __shfl_xor_sync(0xffffffffu, acc[i], 16);
    }

    if (eg == 0) {
        float4 b0 = ((const float4*)b)[f * 2];
        float4 b1 = ((const float4*)b)[f * 2 + 1];
        float o[8];
        o[0] = acc[0] * nv + b0.x; o[1] = acc[1] * nv + b0.y;
        o[2] = acc[2] * nv + b0.z; o[3] = acc[3] * nv + b0.w;
        o[4] = acc[4] * nv + b1.x; o[5] = acc[5] * nv + b1.y;
        o[6] = acc[6] * nv + b1.z; o[7] = acc[7] * nv + b1.w;
        if (do_relu) {
#pragma unroll
            for (int i = 0; i < 8; i++) o[i] = fmaxf(o[i], 0.f);
        }
        if (HOUT) {
            uint4 pk = make_uint4(qpack(o[0], o[1]), qpack(o[2], o[3]),
                                  qpack(o[4], o[5]), qpack(o[6], o[7]));
            *(uint4*)((__half*)outv + (size_t)d * FD + f * 8) = pk;
        } else {
            float* op = (float*)outv + (size_t)d * FD + f * 8;
            *(float4*)op       = make_float4(o[0], o[1], o[2], o[3]);
            *(float4*)(op + 4) = make_float4(o[4], o[5], o[6], o[7]);
        }
    }
}

// ---------------- single-pass GAT: 4 edge groups x 8 lanes; lane f = head f ----------------
__global__ void __launch_bounds__(256) k_gat1(const __half* __restrict__ hg,
                                              __half* __restrict__ out,
                                              const float* __restrict__ bg) {
    int warp = (blockIdx.x * blockDim.x + threadIdx.x) >> 5;
    int lane = threadIdx.x & 31;
    if (warp >= NN) return;
    int d = warp;
    int f = lane & 7, eg = lane >> 3;
    int beg = g_rowptr[d], end = g_rowptr[d + 1];

    float ad_f = g_ad[(size_t)d * NHD + f];
    float acc[8];
#pragma unroll
    for (int i = 0; i < 8; i++) acc[i] = 0.f;
    float z = 0.f;
    if (eg == 0) {   // self loop
        float as_d = g_as[(size_t)d * NHD + f];
        float ps = __expf(lrelu(as_d + ad_f));
        z = ps;
        uint4 hv = *(const uint4*)(hg + (size_t)d * FD + f * 8);
        const __half2* hp = (const __half2*)&hv;
#pragma unroll
        for (int i = 0; i < 4; i++) {
            float2 v = __half22float2(hp[i]);
            acc[i * 2] += ps * v.x; acc[i * 2 + 1] += ps * v.y;
        }
    }

    int niter = (end - beg + 3) >> 2;
    int idx = beg + eg;
    int s = (idx < end) ? g_csrc[idx] : -1;
    for (int t = 0; t < niter; t++) {
        int idx2 = idx + 4;
        int s2 = (idx2 < end) ? g_csrc[idx2] : -1;
        if (s >= 0) {
            float asv = g_as[(size_t)s * NHD + f];
            uint4 v = *(const uint4*)(hg + (size_t)s * FD + f * 8);
            float p = __expf(lrelu(asv + ad_f));
            z += p;
            const __half2* hp = (const __half2*)&v;
#pragma unroll
            for (int i = 0; i < 4; i++) {
                float2 w = __half22float2(hp[i]);
                acc[i * 2] += p * w.x; acc[i * 2 + 1] += p * w.y;
            }
        }
        s = s2; idx = idx2;
    }

    // merge the 4 edge groups
    z += __shfl_xor_sync(0xffffffffu, z, 8);
    z += __shfl_xor_sync(0xffffffffu, z, 16);
#pragma unroll
    for (int i = 0; i < 8; i++) {
        acc[i] += __shfl_xor_sync(0xffffffffu, acc[i], 8);
        acc[i] += __shfl_xor_sync(0xffffffffu, acc[i], 16);
    }

    if (eg == 0) {
        float zi = 1.0f / z;
        float4 b0 = ((const float4*)bg)[f * 2];
        float4 b1 = ((const float4*)bg)[f * 2 + 1];
        float o[8];
        o[0] = fmaxf(acc[0] * zi + b0.x, 0.f); o[1] = fmaxf(acc[1] * zi + b0.y, 0.f);
        o[2] = fmaxf(acc[2] * zi + b0.z, 0.f); o[3] = fmaxf(acc[3] * zi + b0.w, 0.f);
        o[4] = fmaxf(acc[4] * zi + b1.x, 0.f); o[5] = fmaxf(acc[5] * zi + b1.y, 0.f);
        o[6] = fmaxf(acc[6] * zi + b1.z, 0.f); o[7] = fmaxf(acc[7] * zi + b1.w, 0.f);
        uint4 pk = make_uint4(qpack(o[0], o[1]), qpack(o[2], o[3]),
                              qpack(o[4], o[5]), qpack(o[6], o[7]));
        *(uint4*)(out + (size_t)d * FD + f * 8) = pk;
    }
}

// ---------------- driver ----------------
extern "C" void kernel_launch(void* const* d_in, const int* in_sizes, int n_in,
                              void* d_out, int out_size) {
    const float* x    = (const float*)d_in[0];
    const int*   ei   = (const int*)d_in[1];
    const float* W0   = (const float*)d_in[2];
    const float* b0   = (const float*)d_in[3];
    const float* Wg   = (const float*)d_in[4];
    const float* Asrc = (const float*)d_in[5];
    const float* Adst = (const float*)d_in[6];
    const float* bg   = (const float*)d_in[7];
    const float* W2   = (const float*)d_in[8];
    const float* b2   = (const float*)d_in[9];
    const float* W3   = (const float*)d_in[10];
    const float* b3   = (const float*)d_in[11];
    const int* src = ei;
    const int* dst = ei + EE;

    __half* t16; cudaGetSymbolAddress((void**)&t16, g_t);
    __half* h16; cudaGetSymbolAddress((void**)&h16, g_h);
    __half* w16; cudaGetSymbolAddress((void**)&w16, g_w16);
    float* outp = (float*)d_out;

    const int T = 256;
    const int gN    = CDIV(NN, T);
    const int gE4   = CDIV(ESTRIDE, T);
    const int gGemm = CDIV(NN, 128);
    const int gWarp = CDIV(NN * 32, T);

    // side stream + events for CSR/GEMM0 overlap (leaked; kernel_launch runs twice total)
    cudaStream_t s2;
    cudaStreamCreateWithFlags(&s2, cudaStreamNonBlocking);
    cudaEvent_t evF, evJ;
    cudaEventCreateWithFlags(&evF, cudaEventDisableTiming);
    cudaEventCreateWithFlags(&evJ, cudaEventDisableTiming);

    // ---- weight conversion + zeroing (common root) ----
    k_w2h<<<gN, T>>>(W0, Wg, W2, W3);

    // ---- fork: CSR build on s2, layer-0 GEMM (unscaled) on main stream ----
    cudaEventRecord(evF, 0);
    cudaStreamWaitEvent(s2, evF, 0);
    k_deg<<<gE4, T, 0, s2>>>(dst);
    k_scan_lb<<<NB, 256, 0, s2>>>();
    k_scatter<<<gE4, T, 0, s2>>>(src, dst);
    cudaEventRecord(evJ, s2);

    k_gemm_mma<128, 0, 1, 0><<<gGemm, 128>>>(x, w16, t16, nullptr, nullptr);

    // ---- join, then layer 0 gather (applies dinv[s] per edge) ----
    cudaStreamWaitEvent(0, evJ, 0);
    k_gcn_gather<1, 1><<<gWarp, T>>>(t16, h16, b0, 1);

    // ---- layer 1: GAT(64 -> 8x8 concat) + relu; alphas fused into GEMM epilogue ----
    k_gemm_mma<64, 0, 0, 1><<<gGemm, 128>>>(h16, w16 + 8192, t16, Asrc, Adst);
    k_gat1<<<gWarp, T>>>(t16, h16, bg);

    // ---- layer 2: GCN(64->64) + relu ----
    k_gemm_mma<64, 1, 0, 0><<<gGemm, 128>>>(h16, w16 + 12288, t16, nullptr, nullptr);
    k_gcn_gather<1, 0><<<gWarp, T>>>(t16, h16, b2, 1);

    // ---- layer 3: GCN(64->64) into d_out, no relu ----
    k_gemm_mma<64, 1, 0, 0><<<gGemm, 128>>>(h16, w16 + 16384, t16, nullptr, nullptr);
    k_gcn_gather<0, 0><<<gWarp, T>>>(t16, outp, b3, 0);
}